// round 4
// baseline (speedup 1.0000x reference)
#include <cuda_runtime.h>
#include <math.h>

#define HEADS 8
#define HD    32
#define CH    256
#define DIM   96
#define BATCH 2
#define NVOX  32768
#define CM    8

#define GAP_THR 2e-4f      /* fp32 top-2 gap below which we re-decide in fp64 */
#define THETA   5e-7       /* fp64 gap below which we blend the two candidates */
#define MAXFIX  1024

// ---------------- device scratch ----------------
__device__ double g_pool[BATCH][DIM][CM];
__device__ float  g_cf[BATCH*HEADS][CM][HD];        // normalized f-centers (fp32)
__device__ double g_cfd[BATCH*HEADS][CM*HD];        // normalized f-centers (fp64)
__device__ float  g_cv[BATCH*HEADS][CM][HD];        // v-centers
__device__ float  g_num[BATCH*HEADS][CM][HD];
__device__ float  g_den[BATCH*HEADS][CM];
__device__ float  g_sim[BATCH*HEADS][NVOX];         // (weighted) sim of primary center
__device__ unsigned char g_idx[BATCH*HEADS][NVOX];
__device__ float  g_P[BATCH*HEADS][CM][96];

struct FixEntry { int bh, n, m; float wsv; };
__device__ FixEntry g_fix[MAXFIX];
__device__ int g_nfix;

// ---------------- kernel 1a: block-mean pool of PET (fp64) ----------------
__global__ void k_pool(const float* __restrict__ PET) {
    int x = blockIdx.x;
    int t = threadIdx.x;
    if (x == 0) {
        for (int i = t; i < BATCH*HEADS*CM*HD; i += 128) ((float*)g_num)[i] = 0.f;
        for (int i = t; i < BATCH*HEADS*CM;    i += 128) ((float*)g_den)[i] = 0.f;
        if (t == 0) g_nfix = 0;
    }
    int m = x & 7;
    int c = (x >> 3) % 96;
    int b = x / (8 * 96);
    int pw = m >> 2, ph = (m >> 1) & 1, pd = m & 1;
    const float* base = PET + (((size_t)(b * 96 + c)) << 15)
                      + (pw << 4) * 1024 + (ph << 4) * 32 + (pd << 4);
    int k  = t & 15;
    int jj = t >> 4;
    double s = 0.0;
    #pragma unroll
    for (int i = 0; i < 16; i++) {
        s += (double)base[i * 1024 + jj * 32 + k];
        s += (double)base[i * 1024 + (jj + 8) * 32 + k];
    }
    __shared__ double red[128];
    red[t] = s;
    __syncthreads();
    for (int off = 64; off; off >>= 1) {
        if (t < off) red[t] += red[t + off];
        __syncthreads();
    }
    if (t == 0) g_pool[b][c][m] = red[0] * (1.0 / 4096.0);
}

// ---------------- kernel 1b: centers (fp64) ----------------
__global__ void k_centers(const float* __restrict__ fw, const float* __restrict__ fb,
                          const float* __restrict__ vw, const float* __restrict__ vb) {
    __shared__ double pool_s[BATCH][DIM][CM];
    int t = threadIdx.x;  // 256
    for (int i = t; i < BATCH * DIM * CM; i += 256)
        ((double*)pool_s)[i] = ((double*)g_pool)[i];
    __syncthreads();

    int oc = t;
    int h  = oc >> 5;
    int c  = oc & 31;
    for (int b = 0; b < BATCH; b++) {
        double accf[8], accv[8];
        double bf_ = (double)fb[oc], bv_ = (double)vb[oc];
        #pragma unroll
        for (int m = 0; m < 8; m++) { accf[m] = bf_; accv[m] = bv_; }
        for (int k = 0; k < 96; k++) {
            double wfk = (double)fw[oc * 96 + k];
            double wvk = (double)vw[oc * 96 + k];
            #pragma unroll
            for (int m = 0; m < 8; m++) {
                double p = pool_s[b][k][m];
                accf[m] += wfk * p;
                accv[m] += wvk * p;
            }
        }
        int bh = b * 8 + h;
        #pragma unroll
        for (int m = 0; m < 8; m++) {
            double x = accf[m];
            double ss = x * x;
            #pragma unroll
            for (int off = 16; off; off >>= 1)
                ss += __shfl_xor_sync(0xffffffffu, ss, off);
            double inv = 1.0 / fmax(sqrt(ss), 1e-12);
            double cf = x * inv;
            g_cfd[bh][m * 32 + c] = cf;
            g_cf[bh][m][c] = (float)cf;
            g_cv[bh][m][c] = (float)accv[m];
        }
    }
}

// ---------------- kernel 2: main fused conv + sim + argmax + aggregate ----------------
#define SM_CFD   0
#define SM_MRI   512
#define SM_WF    (SM_MRI + 256 * 100)
#define SM_WV    (SM_WF + 3072)
#define SM_CF    (SM_WV + 3072)
#define SM_BF    (SM_CF + 256)
#define SM_BV    (SM_BF + 32)
#define SM_NUM   (SM_BV + 32)
#define SM_DEN   (SM_NUM + 256)
#define SM_MAIN_FLOATS (SM_DEN + 8)

__global__ void __launch_bounds__(256, 1)
k_main(const float* __restrict__ MRI,
       const float* __restrict__ fw, const float* __restrict__ fb,
       const float* __restrict__ vw, const float* __restrict__ vb,
       const float* __restrict__ alpha, const float* __restrict__ beta) {
    extern __shared__ float sm[];
    double* s_cfd = (double*)(sm + SM_CFD);
    float* s_mri = sm + SM_MRI;
    float* s_wf  = sm + SM_WF;
    float* s_wv  = sm + SM_WV;
    float* s_cf  = sm + SM_CF;
    float* s_bf  = sm + SM_BF;
    float* s_bv  = sm + SM_BV;
    float* s_num = sm + SM_NUM;
    float* s_den = sm + SM_DEN;

    int t  = threadIdx.x;
    int b  = blockIdx.z;
    int h  = blockIdx.y;
    int bh = b * 8 + h;
    int n0 = blockIdx.x << 8;

    for (int i = t; i < 96 * 256; i += 256) {
        int k = i >> 8, v = i & 255;
        s_mri[v * 100 + k] = MRI[(((size_t)(b * 96 + k)) << 15) + n0 + v];
    }
    for (int i = t; i < 3072; i += 256) {
        s_wf[i] = fw[h * 3072 + i];
        s_wv[i] = vw[h * 3072 + i];
    }
    s_cf[t] = ((const float*)g_cf)[bh * 256 + t];
    s_cfd[t] = g_cfd[bh][t];
    if (t < 32) { s_bf[t] = fb[h * 32 + t]; s_bv[t] = vb[h * 32 + t]; }
    s_num[t] = 0.f;
    if (t < 8) s_den[t] = 0.f;
    __syncthreads();

    float af[32], av[32];
    #pragma unroll
    for (int c = 0; c < 32; c++) { af[c] = s_bf[c]; av[c] = s_bv[c]; }

    const float4* m4  = (const float4*)(s_mri + t * 100);
    const float4* wf4 = (const float4*)s_wf;
    const float4* wv4 = (const float4*)s_wv;
    #pragma unroll 1
    for (int kk = 0; kk < 24; kk++) {
        float4 mm = m4[kk];
        #pragma unroll
        for (int c = 0; c < 32; c++) {
            float4 a = wf4[c * 24 + kk];
            af[c] += mm.x * a.x + mm.y * a.y + mm.z * a.z + mm.w * a.w;
            float4 q = wv4[c * 24 + kk];
            av[c] += mm.x * q.x + mm.y * q.y + mm.z * q.z + mm.w * q.w;
        }
    }

    float ss = 0.f;
    #pragma unroll
    for (int c = 0; c < 32; c++) ss += af[c] * af[c];
    float inv = 1.f / fmaxf(sqrtf(ss), 1e-12f);
    float al = alpha[0], be = beta[0];

    float best = -1e30f, second = -1e30f;
    int bi = 0;
    #pragma unroll
    for (int mm_ = 0; mm_ < 8; mm_++) {
        float d = 0.f;
        #pragma unroll
        for (int c = 0; c < 32; c++) d += s_cf[mm_ * 32 + c] * af[c];
        float tt = be + al * (d * inv);
        if (tt > best) { second = best; best = tt; bi = mm_; }
        else if (tt > second) second = tt;
    }

    float sv;          // full sv of primary (for aggregation)
    float sv_disp;     // weighted sv for dispatch

    if (best - second >= GAP_THR) {
        sv = 1.f / (1.f + expf(-best));
        sv_disp = sv;
    } else {
        // fp64 re-decision + near-tie blending
        double afd[32];
        #pragma unroll
        for (int c = 0; c < 32; c++) afd[c] = (double)s_bf[c];
        #pragma unroll 1
        for (int k = 0; k < 96; k++) {
            double mk = (double)s_mri[t * 100 + k];
            #pragma unroll
            for (int c = 0; c < 32; c++)
                afd[c] += (double)s_wf[c * 96 + k] * mk;
        }
        double ssd = 0.0;
        #pragma unroll
        for (int c = 0; c < 32; c++) ssd += afd[c] * afd[c];
        double invd = 1.0 / fmax(sqrt(ssd), 1e-12);
        double ald = (double)al, bed = (double)be;

        double z1 = -1e300, z2 = -1e300;
        int m1 = 0, m2 = 0;
        #pragma unroll 1
        for (int mm_ = 0; mm_ < 8; mm_++) {
            double dd = 0.0;
            #pragma unroll
            for (int c = 0; c < 32; c++) dd += s_cfd[mm_ * 32 + c] * afd[c];
            double zz = bed + ald * (dd * invd);
            if (zz > z1) { z2 = z1; m2 = m1; z1 = zz; m1 = mm_; }
            else if (zz > z2) { z2 = zz; m2 = mm_; }
        }
        bi = m1;
        sv = 1.f / (1.f + expf(-(float)z1));
        double g = z1 - z2;
        if (g < THETA) {
            float w = 0.5f + 0.5f * (float)(g / THETA);
            float sv2 = 1.f / (1.f + expf(-(float)z2));
            int slot = atomicAdd(&g_nfix, 1);
            if (slot < MAXFIX) {
                g_fix[slot].bh  = bh;
                g_fix[slot].n   = n0 + t;
                g_fix[slot].m   = m2;
                g_fix[slot].wsv = (1.f - w) * sv2;
            }
            sv_disp = w * sv;
        } else {
            sv_disp = sv;
        }
    }

    g_sim[bh][n0 + t] = sv_disp;
    g_idx[bh][n0 + t] = (unsigned char)bi;

    #pragma unroll
    for (int c = 0; c < 32; c++) atomicAdd(&s_num[bi * 32 + c], sv * av[c]);
    atomicAdd(&s_den[bi], sv);
    __syncthreads();
    atomicAdd(&((float*)g_num)[bh * 256 + t], s_num[t]);
    if (t < 8) atomicAdd(&g_den[bh][t], s_den[t]);
}

// ---------------- kernel 3: agg + fold proj into P ----------------
#define SMP_PROJ  0
#define SMP_AGG   (256 * 97)
#define SM_P_FLOATS (SMP_AGG + 4096)

__global__ void k_P(const float* __restrict__ proj_w) {
    extern __shared__ float smp[];
    float* proj_t = smp + SMP_PROJ;
    float* agg    = smp + SMP_AGG;
    int t = threadIdx.x;  // 256

    for (int i = t; i < 96 * 256; i += 256) {
        int o = i >> 8, cg = i & 255;
        proj_t[cg * 97 + o] = proj_w[i];
    }
    for (int i = t; i < 4096; i += 256) {
        int bh = i >> 8, m = (i >> 5) & 7;
        agg[i] = (((float*)g_num)[i] + ((float*)g_cv)[i]) / (g_den[bh][m] + 1.f);
    }
    __syncthreads();
    for (int j = t; j < 16 * 8 * 96; j += 256) {
        int o  = j % 96;
        int m  = (j / 96) & 7;
        int bh = j / 768;
        int h  = bh & 7;
        float p = 0.f;
        #pragma unroll
        for (int c = 0; c < 32; c++)
            p += proj_t[(h * 32 + c) * 97 + o] * agg[(bh * 8 + m) * 32 + c];
        ((float*)g_P)[j] = p;
    }
}

// ---------------- kernel 4: dispatch + write output ----------------
__global__ void __launch_bounds__(256)
k_out(const float* __restrict__ proj_b, float* __restrict__ out) {
    __shared__ __align__(16) float P_s[8][8][104];
    __shared__ float sim_s[8][256];
    __shared__ unsigned char idx_s[8][256];
    __shared__ float pb_s[96];
    int t  = threadIdx.x;
    int b  = blockIdx.y;
    int n0 = blockIdx.x << 8;

    for (int i = t; i < 8 * 8 * 96; i += 256) {
        int o = i % 96, m = (i / 96) & 7, h = i / 768;
        P_s[h][m][o] = ((float*)g_P)[((b * 8 + h) * 8 + m) * 96 + o];
    }
    for (int i = t; i < 8 * 256; i += 256) {
        int h = i >> 8, v = i & 255;
        sim_s[h][v] = g_sim[b * 8 + h][n0 + v];
        idx_s[h][v] = g_idx[b * 8 + h][n0 + v];
    }
    if (t < 96) pb_s[t] = proj_b[t];
    __syncthreads();

    float acc[96];
    #pragma unroll
    for (int o = 0; o < 96; o++) acc[o] = pb_s[o];

    #pragma unroll
    for (int h = 0; h < 8; h++) {
        float s = sim_s[h][t];
        const float4* Pb = (const float4*)&P_s[h][idx_s[h][t]][0];
        #pragma unroll
        for (int o4 = 0; o4 < 24; o4++) {
            float4 p = Pb[o4];
            acc[o4 * 4 + 0] += s * p.x;
            acc[o4 * 4 + 1] += s * p.y;
            acc[o4 * 4 + 2] += s * p.z;
            acc[o4 * 4 + 3] += s * p.w;
        }
    }
    size_t n = (size_t)n0 + t;
    #pragma unroll
    for (int o = 0; o < 96; o++)
        out[(((size_t)(b * 96 + o)) << 15) + n] = acc[o];
}

// ---------------- kernel 5: secondary-candidate fixups ----------------
// grid 8 blocks x 96 threads; grid-stride over the (tiny) fix list
__global__ void k_fix(const float* __restrict__ proj_w, float* __restrict__ out) {
    int nf = g_nfix;
    if (nf > MAXFIX) nf = MAXFIX;
    int o = threadIdx.x;   // 0..95
    for (int e = blockIdx.x; e < nf; e += gridDim.x) {
        FixEntry f = g_fix[e];
        int bh = f.bh, h = bh & 7, b = bh >> 3, m = f.m;
        float den = g_den[bh][m] + 1.f;
        float p = 0.f;
        #pragma unroll
        for (int c = 0; c < 32; c++) {
            float agg = (g_num[bh][m][c] + g_cv[bh][m][c]) / den;
            p += proj_w[o * 256 + h * 32 + c] * agg;
        }
        atomicAdd(&out[(((size_t)(b * 96 + o)) << 15) + f.n], f.wsv * p);
    }
}

// ---------------- launch ----------------
extern "C" void kernel_launch(void* const* d_in, const int* in_sizes, int n_in,
                              void* d_out, int out_size) {
    const float* PET     = (const float*)d_in[0];
    const float* MRI     = (const float*)d_in[1];
    const float* f_pet_w = (const float*)d_in[2];
    const float* f_pet_b = (const float*)d_in[3];
    const float* f_mri_w = (const float*)d_in[4];
    const float* f_mri_b = (const float*)d_in[5];
    const float* v_pet_w = (const float*)d_in[6];
    const float* v_pet_b = (const float*)d_in[7];
    const float* v_mri_w = (const float*)d_in[8];
    const float* v_mri_b = (const float*)d_in[9];
    const float* proj_w  = (const float*)d_in[10];
    const float* proj_b  = (const float*)d_in[11];
    const float* alpha   = (const float*)d_in[12];
    const float* beta    = (const float*)d_in[13];
    float* out = (float*)d_out;

    size_t smem_main = SM_MAIN_FLOATS * sizeof(float);
    size_t smem_p    = SM_P_FLOATS * sizeof(float);
    cudaFuncSetAttribute(k_main, cudaFuncAttributeMaxDynamicSharedMemorySize, (int)smem_main);
    cudaFuncSetAttribute(k_P,    cudaFuncAttributeMaxDynamicSharedMemorySize, (int)smem_p);

    k_pool<<<1536, 128>>>(PET);
    k_centers<<<1, 256>>>(f_pet_w, f_pet_b, v_pet_w, v_pet_b);
    k_main<<<dim3(128, 8, 2), 256, smem_main>>>(MRI, f_mri_w, f_mri_b,
                                                v_mri_w, v_mri_b, alpha, beta);
    k_P<<<1, 256, smem_p>>>(proj_w);
    k_out<<<dim3(128, 2), 256>>>(proj_b, out);
    k_fix<<<8, 96>>>(proj_w, out);
}

// round 5
// speedup vs baseline: 3.9645x; 3.9645x over previous
#include <cuda_runtime.h>
#include <math.h>

#define HEADS 8
#define HD    32
#define CH    256
#define DIM   96
#define BATCH 2
#define NVOX  32768
#define CM    8

#define GAP_THR 1e-4f      /* fp32 top-2 gap below which we re-decide precisely */
#define THETA   5e-7       /* precise gap below which we blend the two candidates */
#define MAXFIX  1024

// ---------------- double-float helpers (FFMA pipe, ~1e-13 accuracy) ----------------
struct dfloat { float hi, lo; };

__device__ __forceinline__ dfloat df_add(dfloat s, float x) {
    float t  = s.hi + x;
    float bv = t - s.hi;
    float err = (s.hi - (t - bv)) + (x - bv);
    dfloat r; r.hi = t; r.lo = s.lo + err; return r;
}
__device__ __forceinline__ dfloat df2_add(dfloat a, dfloat b) {
    float t  = a.hi + b.hi;
    float d  = t - a.hi;
    float err = (a.hi - (t - d)) + (b.hi - d);
    dfloat r; r.hi = t; r.lo = a.lo + b.lo + err; return r;
}
// s += a * b  (a fp32 exact, b fp32)
__device__ __forceinline__ dfloat df_addp1(dfloat s, float a, float b) {
    float p = a * b;
    float e = fmaf(a, b, -p);
    float t = s.hi + p;
    float d = t - s.hi;
    float err = (s.hi - (t - d)) + (p - d);
    dfloat r; r.hi = t; r.lo = s.lo + (err + e); return r;
}
// s += a * (b.hi + b.lo)
__device__ __forceinline__ dfloat df_addp(dfloat s, float a, dfloat b) {
    float p = a * b.hi;
    float e = fmaf(a, b.hi, -p);
    e = fmaf(a, b.lo, e);
    float t = s.hi + p;
    float d = t - s.hi;
    float err = (s.hi - (t - d)) + (p - d);
    dfloat r; r.hi = t; r.lo = s.lo + (err + e); return r;
}

// ---------------- packed f32x2 helpers ----------------
__device__ __forceinline__ unsigned long long pack2(float lo, float hi) {
    unsigned long long r;
    asm("mov.b64 %0, {%1, %2};" : "=l"(r) : "f"(lo), "f"(hi));
    return r;
}
__device__ __forceinline__ void unpack2(unsigned long long v, float& lo, float& hi) {
    asm("mov.b64 {%0, %1}, %2;" : "=f"(lo), "=f"(hi) : "l"(v));
}
__device__ __forceinline__ unsigned long long fma2(unsigned long long a,
                                                   unsigned long long b,
                                                   unsigned long long c) {
    unsigned long long d;
    asm("fma.rn.f32x2 %0, %1, %2, %3;" : "=l"(d) : "l"(a), "l"(b), "l"(c));
    return d;
}

// ---------------- device scratch ----------------
__device__ double g_pool[BATCH][DIM][CM];
__device__ float  g_cf[BATCH*HEADS][CM][HD];
__device__ double g_cfd[BATCH*HEADS][CM*HD];
__device__ float  g_cv[BATCH*HEADS][CM][HD];
__device__ float  g_num[BATCH*HEADS][CM][HD];
__device__ float  g_den[BATCH*HEADS][CM];
__device__ float  g_sim[BATCH*HEADS][NVOX];
__device__ unsigned char g_idx[BATCH*HEADS][NVOX];
__device__ float  g_P[BATCH*HEADS][CM][96];

struct FixEntry { int bh, n, m; float wsv; };
__device__ FixEntry g_fix[MAXFIX];
__device__ int g_nfix;

// ---------------- kernel 1a: block-mean pool of PET (df64 on FFMA pipe) ----------------
__global__ void k_pool(const float* __restrict__ PET) {
    int x = blockIdx.x;
    int t = threadIdx.x;
    if (x == 0) {
        for (int i = t; i < BATCH*HEADS*CM*HD; i += 128) ((float*)g_num)[i] = 0.f;
        for (int i = t; i < BATCH*HEADS*CM;    i += 128) ((float*)g_den)[i] = 0.f;
        if (t == 0) g_nfix = 0;
    }
    int m = x & 7;
    int c = (x >> 3) % 96;
    int b = x / (8 * 96);
    int pw = m >> 2, ph = (m >> 1) & 1, pd = m & 1;
    const float* base = PET + (((size_t)(b * 96 + c)) << 15)
                      + (pw << 4) * 1024 + (ph << 4) * 32 + (pd << 4);
    int k  = t & 15;
    int jj = t >> 4;
    dfloat s; s.hi = 0.f; s.lo = 0.f;
    #pragma unroll
    for (int i = 0; i < 16; i++) {
        s = df_add(s, base[i * 1024 + jj * 32 + k]);
        s = df_add(s, base[i * 1024 + (jj + 8) * 32 + k]);
    }
    __shared__ float redh[128], redl[128];
    redh[t] = s.hi; redl[t] = s.lo;
    __syncthreads();
    for (int off = 64; off; off >>= 1) {
        if (t < off) {
            dfloat a; a.hi = redh[t]; a.lo = redl[t];
            dfloat bb; bb.hi = redh[t + off]; bb.lo = redl[t + off];
            dfloat r = df2_add(a, bb);
            redh[t] = r.hi; redl[t] = r.lo;
        }
        __syncthreads();
    }
    if (t == 0)
        g_pool[b][c][m] = ((double)redh[0] + (double)redl[0]) * (1.0 / 4096.0);
}

// ---------------- kernel 1b: centers (df64 accumulate) ----------------
// grid 16 (= bh), 256 threads: warp == m, lanes == c
__global__ void k_centers(const float* __restrict__ fw, const float* __restrict__ fb,
                          const float* __restrict__ vw, const float* __restrict__ vb) {
    __shared__ float s_fw[32 * 97];
    __shared__ float s_vw[32 * 97];
    __shared__ float ph[DIM * CM], pl[DIM * CM];
    int bh = blockIdx.x;
    int b = bh >> 3, h = bh & 7;
    int t = threadIdx.x;
    int m = t >> 5, c = t & 31;

    for (int i = t; i < 3072; i += 256) {
        int cc = i / 96, k = i % 96;
        s_fw[cc * 97 + k] = fw[h * 3072 + i];
        s_vw[cc * 97 + k] = vw[h * 3072 + i];
    }
    for (int i = t; i < DIM * CM; i += 256) {
        double d = ((const double*)g_pool)[b * DIM * CM + i];
        float hi = (float)d;
        ph[i] = hi; pl[i] = (float)(d - (double)hi);
    }
    __syncthreads();

    int oc = h * 32 + c;
    dfloat F; F.hi = fb[oc]; F.lo = 0.f;
    dfloat V; V.hi = vb[oc]; V.lo = 0.f;
    #pragma unroll 4
    for (int k = 0; k < 96; k++) {
        dfloat p; p.hi = ph[k * 8 + m]; p.lo = pl[k * 8 + m];
        F = df_addp(F, s_fw[c * 97 + k], p);
        V = df_addp(V, s_vw[c * 97 + k], p);
    }
    double accf = (double)F.hi + (double)F.lo;
    double accv = (double)V.hi + (double)V.lo;
    double ss = accf * accf;
    #pragma unroll
    for (int off = 16; off; off >>= 1)
        ss += __shfl_xor_sync(0xffffffffu, ss, off);
    double inv = 1.0 / fmax(sqrt(ss), 1e-12);
    double cf = accf * inv;
    g_cfd[bh][m * 32 + c] = cf;
    g_cf[bh][m][c] = (float)cf;
    g_cv[bh][m][c] = (float)accv;
}

// ---------------- kernel 2: main fused conv + sim + argmax + aggregate ----------------
#define SM_CFD   0                       // 256 doubles = 512 float slots
#define SM_MRI   512                     // 256*101
#define SM_W2    (SM_MRI + 256 * 101)    // 96 rows * 64 floats ([f0..f31, v0..v31])
#define SM_CF    (SM_W2 + 96 * 64)
#define SM_BF    (SM_CF + 256)
#define SM_BV    (SM_BF + 32)
#define SM_NUM4  (SM_BV + 32)            // 4 * 256
#define SM_DEN4  (SM_NUM4 + 1024)        // 4 * 8
#define SM_MAIN_FLOATS (SM_DEN4 + 32)

__global__ void __launch_bounds__(256, 1)
k_main(const float* __restrict__ MRI,
       const float* __restrict__ fw, const float* __restrict__ fb,
       const float* __restrict__ vw, const float* __restrict__ vb,
       const float* __restrict__ alpha, const float* __restrict__ beta) {
    extern __shared__ float sm[];
    double* s_cfd = (double*)(sm + SM_CFD);
    float* s_mri  = sm + SM_MRI;
    float* s_w2   = sm + SM_W2;
    float* s_cf   = sm + SM_CF;
    float* s_bf   = sm + SM_BF;
    float* s_bv   = sm + SM_BV;
    float* s_num4 = sm + SM_NUM4;
    float* s_den4 = sm + SM_DEN4;

    int t  = threadIdx.x;
    int b  = blockIdx.z;
    int h  = blockIdx.y;
    int bh = b * 8 + h;
    int n0 = blockIdx.x << 8;

    for (int i = t; i < 96 * 256; i += 256) {
        int k = i >> 8, v = i & 255;
        s_mri[v * 101 + k] = MRI[(((size_t)(b * 96 + k)) << 15) + n0 + v];
    }
    for (int i = t; i < 3072; i += 256) {
        int c = i / 96, k = i % 96;
        s_w2[k * 64 + c]      = fw[h * 3072 + i];
        s_w2[k * 64 + 32 + c] = vw[h * 3072 + i];
    }
    s_cf[t] = ((const float*)g_cf)[bh * 256 + t];
    s_cfd[t] = g_cfd[bh][t];
    if (t < 32) { s_bf[t] = fb[h * 32 + t]; s_bv[t] = vb[h * 32 + t]; }
    for (int i = t; i < 1024; i += 256) s_num4[i] = 0.f;
    if (t < 32) s_den4[t] = 0.f;
    __syncthreads();

    // fused fM / vM conv in packed f32x2 (per-channel chains, bias-first)
    unsigned long long AF[16], AV[16];
    #pragma unroll
    for (int j = 0; j < 16; j++) {
        AF[j] = pack2(s_bf[2*j], s_bf[2*j+1]);
        AV[j] = pack2(s_bv[2*j], s_bv[2*j+1]);
    }
    const float* mrow = s_mri + t * 101;
    #pragma unroll 2
    for (int k = 0; k < 96; k++) {
        float mk = mrow[k];
        unsigned long long m2 = pack2(mk, mk);
        const ulonglong2* wf = (const ulonglong2*)(s_w2 + k * 64);
        const ulonglong2* wv = (const ulonglong2*)(s_w2 + k * 64 + 32);
        #pragma unroll
        for (int j = 0; j < 8; j++) {
            ulonglong2 a = wf[j];
            AF[2*j]   = fma2(m2, a.x, AF[2*j]);
            AF[2*j+1] = fma2(m2, a.y, AF[2*j+1]);
        }
        #pragma unroll
        for (int j = 0; j < 8; j++) {
            ulonglong2 q = wv[j];
            AV[2*j]   = fma2(m2, q.x, AV[2*j]);
            AV[2*j+1] = fma2(m2, q.y, AV[2*j+1]);
        }
    }
    float af[32], av[32];
    #pragma unroll
    for (int j = 0; j < 16; j++) {
        unpack2(AF[j], af[2*j], af[2*j+1]);
        unpack2(AV[j], av[2*j], av[2*j+1]);
    }

    float ss = 0.f;
    #pragma unroll
    for (int c = 0; c < 32; c++) ss += af[c] * af[c];
    float inv = 1.f / fmaxf(sqrtf(ss), 1e-12f);
    float al = alpha[0], be = beta[0];

    float best = -1e30f, second = -1e30f;
    int bi = 0;
    #pragma unroll
    for (int mm_ = 0; mm_ < 8; mm_++) {
        float d = 0.f;
        #pragma unroll
        for (int c = 0; c < 32; c++) d += s_cf[mm_ * 32 + c] * af[c];
        float tt = be + al * (d * inv);
        if (tt > best) { second = best; best = tt; bi = mm_; }
        else if (tt > second) second = tt;
    }

    float sv, sv_disp;
    if (best - second >= GAP_THR) {
        sv = 1.f / (1.f + expf(-best));
        sv_disp = sv;
    } else {
        // precise re-decision: df64 conv on FFMA pipe, tiny fp64 tail
        dfloat D[32];
        #pragma unroll
        for (int c = 0; c < 32; c++) { D[c].hi = s_bf[c]; D[c].lo = 0.f; }
        #pragma unroll 1
        for (int k = 0; k < 96; k++) {
            float mk = mrow[k];
            const float* wrow = s_w2 + k * 64;
            #pragma unroll
            for (int c = 0; c < 32; c++)
                D[c] = df_addp1(D[c], wrow[c], mk);
        }
        double afd[32];
        double ssd = 0.0;
        #pragma unroll
        for (int c = 0; c < 32; c++) {
            afd[c] = (double)D[c].hi + (double)D[c].lo;
            ssd += afd[c] * afd[c];
        }
        double invd = 1.0 / fmax(sqrt(ssd), 1e-12);
        double ald = (double)al, bed = (double)be;

        double z1 = -1e300, z2 = -1e300;
        int m1 = 0, m2 = 0;
        #pragma unroll 1
        for (int mm_ = 0; mm_ < 8; mm_++) {
            double dd = 0.0;
            #pragma unroll
            for (int c = 0; c < 32; c++) dd += s_cfd[mm_ * 32 + c] * afd[c];
            double zz = bed + ald * (dd * invd);
            if (zz > z1) { z2 = z1; m2 = m1; z1 = zz; m1 = mm_; }
            else if (zz > z2) { z2 = zz; m2 = mm_; }
        }
        bi = m1;
        sv = 1.f / (1.f + expf(-(float)z1));
        double g = z1 - z2;
        if (g < THETA) {
            float w = 0.5f + 0.5f * (float)(g / THETA);
            float sv2 = 1.f / (1.f + expf(-(float)z2));
            int slot = atomicAdd(&g_nfix, 1);
            if (slot < MAXFIX) {
                g_fix[slot].bh  = bh;
                g_fix[slot].n   = n0 + t;
                g_fix[slot].m   = m2;
                g_fix[slot].wsv = (1.f - w) * sv2;
            }
            sv_disp = w * sv;
        } else {
            sv_disp = sv;
        }
    }

    g_sim[bh][n0 + t] = sv_disp;
    g_idx[bh][n0 + t] = (unsigned char)bi;

    // block-local aggregate (4 replicas to cut contention), then global atomics
    float* my_num = s_num4 + (t >> 6) * 256;
    float* my_den = s_den4 + (t >> 6) * 8;
    #pragma unroll
    for (int c = 0; c < 32; c++) atomicAdd(&my_num[bi * 32 + c], sv * av[c]);
    atomicAdd(&my_den[bi], sv);
    __syncthreads();
    float tot = s_num4[t] + s_num4[256 + t] + s_num4[512 + t] + s_num4[768 + t];
    atomicAdd(&((float*)g_num)[bh * 256 + t], tot);
    if (t < 8)
        atomicAdd(&g_den[bh][t], s_den4[t] + s_den4[8 + t] + s_den4[16 + t] + s_den4[24 + t]);
}

// ---------------- kernel 3: agg + fold proj into P ----------------
// grid 16 (= bh), 256 threads
__global__ void k_P(const float* __restrict__ proj_w) {
    __shared__ float s_pj[32 * 97];
    __shared__ float s_agg[256];
    int bh = blockIdx.x;
    int h = bh & 7;
    int t = threadIdx.x;

    for (int i = t; i < 32 * 96; i += 256) {
        int c = i & 31, o = i >> 5;
        s_pj[c * 97 + o] = proj_w[o * 256 + h * 32 + c];
    }
    {
        int m = t >> 5;
        s_agg[t] = (((const float*)g_num)[bh * 256 + t] + ((const float*)g_cv)[bh * 256 + t])
                 / (g_den[bh][m] + 1.f);
    }
    __syncthreads();
    for (int j = t; j < 8 * 96; j += 256) {
        int m = j / 96, o = j % 96;
        float p = 0.f;
        #pragma unroll
        for (int c = 0; c < 32; c++)
            p += s_pj[c * 97 + o] * s_agg[m * 32 + c];
        g_P[bh][m][o] = p;
    }
}

// ---------------- kernel 4: dispatch + write output ----------------
__global__ void __launch_bounds__(256)
k_out(const float* __restrict__ proj_b, float* __restrict__ out) {
    __shared__ __align__(16) float P_s[8][8][104];
    __shared__ float sim_s[8][256];
    __shared__ unsigned char idx_s[8][256];
    __shared__ float pb_s[96];
    int t  = threadIdx.x;
    int b  = blockIdx.y;
    int n0 = blockIdx.x << 8;

    for (int i = t; i < 8 * 8 * 96; i += 256) {
        int o = i % 96, m = (i / 96) & 7, h = i / 768;
        P_s[h][m][o] = ((float*)g_P)[((b * 8 + h) * 8 + m) * 96 + o];
    }
    for (int i = t; i < 8 * 256; i += 256) {
        int h = i >> 8, v = i & 255;
        sim_s[h][v] = g_sim[b * 8 + h][n0 + v];
        idx_s[h][v] = g_idx[b * 8 + h][n0 + v];
    }
    if (t < 96) pb_s[t] = proj_b[t];
    __syncthreads();

    float acc[96];
    #pragma unroll
    for (int o = 0; o < 96; o++) acc[o] = pb_s[o];

    #pragma unroll
    for (int h = 0; h < 8; h++) {
        float s = sim_s[h][t];
        const float4* Pb = (const float4*)&P_s[h][idx_s[h][t]][0];
        #pragma unroll
        for (int o4 = 0; o4 < 24; o4++) {
            float4 p = Pb[o4];
            acc[o4 * 4 + 0] += s * p.x;
            acc[o4 * 4 + 1] += s * p.y;
            acc[o4 * 4 + 2] += s * p.z;
            acc[o4 * 4 + 3] += s * p.w;
        }
    }
    size_t n = (size_t)n0 + t;
    #pragma unroll
    for (int o = 0; o < 96; o++)
        out[(((size_t)(b * 96 + o)) << 15) + n] = acc[o];
}

// ---------------- kernel 5: secondary-candidate fixups ----------------
__global__ void k_fix(const float* __restrict__ proj_w, float* __restrict__ out) {
    int nf = g_nfix;
    if (nf > MAXFIX) nf = MAXFIX;
    int o = threadIdx.x;   // 0..95
    for (int e = blockIdx.x; e < nf; e += gridDim.x) {
        FixEntry f = g_fix[e];
        int bh = f.bh, h = bh & 7, b = bh >> 3, m = f.m;
        float den = g_den[bh][m] + 1.f;
        float p = 0.f;
        #pragma unroll
        for (int c = 0; c < 32; c++) {
            float agg = (g_num[bh][m][c] + g_cv[bh][m][c]) / den;
            p += proj_w[o * 256 + h * 32 + c] * agg;
        }
        atomicAdd(&out[(((size_t)(b * 96 + o)) << 15) + f.n], f.wsv * p);
    }
}

// ---------------- launch ----------------
extern "C" void kernel_launch(void* const* d_in, const int* in_sizes, int n_in,
                              void* d_out, int out_size) {
    const float* PET     = (const float*)d_in[0];
    const float* MRI     = (const float*)d_in[1];
    const float* f_pet_w = (const float*)d_in[2];
    const float* f_pet_b = (const float*)d_in[3];
    const float* f_mri_w = (const float*)d_in[4];
    const float* f_mri_b = (const float*)d_in[5];
    const float* v_pet_w = (const float*)d_in[6];
    const float* v_pet_b = (const float*)d_in[7];
    const float* v_mri_w = (const float*)d_in[8];
    const float* v_mri_b = (const float*)d_in[9];
    const float* proj_w  = (const float*)d_in[10];
    const float* proj_b  = (const float*)d_in[11];
    const float* alpha   = (const float*)d_in[12];
    const float* beta    = (const float*)d_in[13];
    float* out = (float*)d_out;

    size_t smem_main = SM_MAIN_FLOATS * sizeof(float);   // ~135.6 KB
    cudaFuncSetAttribute(k_main, cudaFuncAttributeMaxDynamicSharedMemorySize, (int)smem_main);

    k_pool<<<1536, 128>>>(PET);
    k_centers<<<16, 256>>>(f_pet_w, f_pet_b, v_pet_w, v_pet_b);
    k_main<<<dim3(128, 8, 2), 256, smem_main>>>(MRI, f_mri_w, f_mri_b,
                                                v_mri_w, v_mri_b, alpha, beta);
    k_P<<<16, 256>>>(proj_w);
    k_out<<<dim3(128, 2), 256>>>(proj_b, out);
    k_fix<<<8, 96>>>(proj_w, out);
}

// round 6
// speedup vs baseline: 5.8005x; 1.4631x over previous
#include <cuda_runtime.h>
#include <math.h>

#define HEADS 8
#define HD    32
#define CH    256
#define DIM   96
#define BATCH 2
#define NVOX  32768
#define CM    8

#define FLAG_THR 2e-6f     /* delta-dot z-gap below which we re-decide in df64/fp64 */
#define THETA    5e-7      /* precise gap below which we blend the two candidates */
#define MAXFIX   1024

// ---------------- double-float helpers (FFMA pipe) ----------------
struct dfloat { float hi, lo; };

__device__ __forceinline__ dfloat df_add(dfloat s, float x) {
    float t  = s.hi + x;
    float bv = t - s.hi;
    float err = (s.hi - (t - bv)) + (x - bv);
    dfloat r; r.hi = t; r.lo = s.lo + err; return r;
}
__device__ __forceinline__ dfloat df2_add(dfloat a, dfloat b) {
    float t  = a.hi + b.hi;
    float d  = t - a.hi;
    float err = (a.hi - (t - d)) + (b.hi - d);
    dfloat r; r.hi = t; r.lo = a.lo + b.lo + err; return r;
}
__device__ __forceinline__ dfloat df_addp1(dfloat s, float a, float b) {
    float p = a * b;
    float e = fmaf(a, b, -p);
    float t = s.hi + p;
    float d = t - s.hi;
    float err = (s.hi - (t - d)) + (p - d);
    dfloat r; r.hi = t; r.lo = s.lo + (err + e); return r;
}
__device__ __forceinline__ dfloat df_addp(dfloat s, float a, dfloat b) {
    float p = a * b.hi;
    float e = fmaf(a, b.hi, -p);
    e = fmaf(a, b.lo, e);
    float t = s.hi + p;
    float d = t - s.hi;
    float err = (s.hi - (t - d)) + (p - d);
    dfloat r; r.hi = t; r.lo = s.lo + (err + e); return r;
}

// ---------------- packed f32x2 helpers ----------------
__device__ __forceinline__ unsigned long long pack2(float lo, float hi) {
    unsigned long long r;
    asm("mov.b64 %0, {%1, %2};" : "=l"(r) : "f"(lo), "f"(hi));
    return r;
}
__device__ __forceinline__ void unpack2(unsigned long long v, float& lo, float& hi) {
    asm("mov.b64 {%0, %1}, %2;" : "=f"(lo), "=f"(hi) : "l"(v));
}
__device__ __forceinline__ unsigned long long fma2(unsigned long long a,
                                                   unsigned long long b,
                                                   unsigned long long c) {
    unsigned long long d;
    asm("fma.rn.f32x2 %0, %1, %2, %3;" : "=l"(d) : "l"(a), "l"(b), "l"(c));
    return d;
}

// ---------------- device scratch ----------------
__device__ double g_pool[BATCH][DIM][CM];
__device__ float  g_cf[BATCH*HEADS][CM][HD];
__device__ double g_cfd[BATCH*HEADS][CM*HD];
__device__ float  g_dc[BATCH*HEADS][CM*HD];     // fp32(cfd[m] - cfd[0]) exact diffs
__device__ float  g_cv[BATCH*HEADS][CM][HD];
__device__ float  g_num[BATCH*HEADS][CM][HD];
__device__ float  g_den[BATCH*HEADS][CM];
__device__ float  g_sim[BATCH*HEADS][NVOX];
__device__ unsigned char g_idx[BATCH*HEADS][NVOX];
__device__ float  g_P[BATCH*HEADS][CM][96];

struct FixEntry { int bh, n, m; float wsv; };
__device__ FixEntry g_fix[MAXFIX];
__device__ int g_nfix;

// ---------------- kernel 1a: block-mean pool of PET (df64) ----------------
__global__ void k_pool(const float* __restrict__ PET) {
    int x = blockIdx.x;
    int t = threadIdx.x;
    if (x == 0) {
        for (int i = t; i < BATCH*HEADS*CM*HD; i += 128) ((float*)g_num)[i] = 0.f;
        for (int i = t; i < BATCH*HEADS*CM;    i += 128) ((float*)g_den)[i] = 0.f;
        if (t == 0) g_nfix = 0;
    }
    int m = x & 7;
    int c = (x >> 3) % 96;
    int b = x / (8 * 96);
    int pw = m >> 2, ph = (m >> 1) & 1, pd = m & 1;
    const float* base = PET + (((size_t)(b * 96 + c)) << 15)
                      + (pw << 4) * 1024 + (ph << 4) * 32 + (pd << 4);
    int k  = t & 15;
    int jj = t >> 4;
    dfloat s; s.hi = 0.f; s.lo = 0.f;
    #pragma unroll
    for (int i = 0; i < 16; i++) {
        s = df_add(s, base[i * 1024 + jj * 32 + k]);
        s = df_add(s, base[i * 1024 + (jj + 8) * 32 + k]);
    }
    __shared__ float redh[128], redl[128];
    redh[t] = s.hi; redl[t] = s.lo;
    __syncthreads();
    for (int off = 64; off; off >>= 1) {
        if (t < off) {
            dfloat a; a.hi = redh[t]; a.lo = redl[t];
            dfloat bb; bb.hi = redh[t + off]; bb.lo = redl[t + off];
            dfloat r = df2_add(a, bb);
            redh[t] = r.hi; redl[t] = r.lo;
        }
        __syncthreads();
    }
    if (t == 0)
        g_pool[b][c][m] = ((double)redh[0] + (double)redl[0]) * (1.0 / 4096.0);
}

// ---------------- kernel 1b: centers (df64 accumulate) + exact center deltas ----------------
// grid 16 (= bh), 256 threads: warp == m, lanes == c
__global__ void k_centers(const float* __restrict__ fw, const float* __restrict__ fb,
                          const float* __restrict__ vw, const float* __restrict__ vb) {
    __shared__ float s_fw[32 * 97];
    __shared__ float s_vw[32 * 97];
    __shared__ float ph[DIM * CM], pl[DIM * CM];
    __shared__ double row0[32];
    int bh = blockIdx.x;
    int b = bh >> 3, h = bh & 7;
    int t = threadIdx.x;
    int m = t >> 5, c = t & 31;

    for (int i = t; i < 3072; i += 256) {
        int cc = i / 96, k = i % 96;
        s_fw[cc * 97 + k] = fw[h * 3072 + i];
        s_vw[cc * 97 + k] = vw[h * 3072 + i];
    }
    for (int i = t; i < DIM * CM; i += 256) {
        double d = ((const double*)g_pool)[b * DIM * CM + i];
        float hi = (float)d;
        ph[i] = hi; pl[i] = (float)(d - (double)hi);
    }
    __syncthreads();

    int oc = h * 32 + c;
    dfloat F; F.hi = fb[oc]; F.lo = 0.f;
    dfloat V; V.hi = vb[oc]; V.lo = 0.f;
    #pragma unroll 4
    for (int k = 0; k < 96; k++) {
        dfloat p; p.hi = ph[k * 8 + m]; p.lo = pl[k * 8 + m];
        F = df_addp(F, s_fw[c * 97 + k], p);
        V = df_addp(V, s_vw[c * 97 + k], p);
    }
    double accf = (double)F.hi + (double)F.lo;
    double accv = (double)V.hi + (double)V.lo;
    double ss = accf * accf;
    #pragma unroll
    for (int off = 16; off; off >>= 1)
        ss += __shfl_xor_sync(0xffffffffu, ss, off);
    double inv = 1.0 / fmax(sqrt(ss), 1e-12);
    double cf = accf * inv;
    g_cfd[bh][m * 32 + c] = cf;
    g_cf[bh][m][c] = (float)cf;
    g_cv[bh][m][c] = (float)accv;
    if (m == 0) row0[c] = cf;
    __syncthreads();
    g_dc[bh][m * 32 + c] = (float)(cf - row0[c]);
}

// ---------------- kernel 2: main fused conv + delta-argmax + aggregate ----------------
#define SM_CFD   0                       // 256 doubles = 512 float slots
#define SM_MRI   512                     // 256*101
#define SM_W2    (SM_MRI + 256 * 101)    // 96 rows * 64 floats ([f0..f31, v0..v31])
#define SM_CF    (SM_W2 + 96 * 64)       // 256 (row 0 used for cos0)
#define SM_DC    (SM_CF + 256)           // 256 center deltas
#define SM_BF    (SM_DC + 256)
#define SM_BV    (SM_BF + 32)
#define SM_NUM4  (SM_BV + 32)            // 4 * 256
#define SM_DEN4  (SM_NUM4 + 1024)        // 4 * 8
#define SM_MAIN_FLOATS (SM_DEN4 + 32)

__global__ void __launch_bounds__(256, 1)
k_main(const float* __restrict__ MRI,
       const float* __restrict__ fw, const float* __restrict__ fb,
       const float* __restrict__ vw, const float* __restrict__ vb,
       const float* __restrict__ alpha, const float* __restrict__ beta) {
    extern __shared__ float sm[];
    double* s_cfd = (double*)(sm + SM_CFD);
    float* s_mri  = sm + SM_MRI;
    float* s_w2   = sm + SM_W2;
    float* s_cf   = sm + SM_CF;
    float* s_dc   = sm + SM_DC;
    float* s_bf   = sm + SM_BF;
    float* s_bv   = sm + SM_BV;
    float* s_num4 = sm + SM_NUM4;
    float* s_den4 = sm + SM_DEN4;

    int t  = threadIdx.x;
    int b  = blockIdx.z;
    int h  = blockIdx.y;
    int bh = b * 8 + h;
    int n0 = blockIdx.x << 8;

    for (int i = t; i < 96 * 256; i += 256) {
        int k = i >> 8, v = i & 255;
        s_mri[v * 101 + k] = MRI[(((size_t)(b * 96 + k)) << 15) + n0 + v];
    }
    for (int i = t; i < 3072; i += 256) {
        int c = i / 96, k = i % 96;
        s_w2[k * 64 + c]      = fw[h * 3072 + i];
        s_w2[k * 64 + 32 + c] = vw[h * 3072 + i];
    }
    s_cf[t] = ((const float*)g_cf)[bh * 256 + t];
    s_dc[t] = ((const float*)g_dc)[bh * 256 + t];
    s_cfd[t] = g_cfd[bh][t];
    if (t < 32) { s_bf[t] = fb[h * 32 + t]; s_bv[t] = vb[h * 32 + t]; }
    for (int i = t; i < 1024; i += 256) s_num4[i] = 0.f;
    if (t < 32) s_den4[t] = 0.f;
    __syncthreads();

    // fused fM / vM conv in packed f32x2
    unsigned long long AF[16], AV[16];
    #pragma unroll
    for (int j = 0; j < 16; j++) {
        AF[j] = pack2(s_bf[2*j], s_bf[2*j+1]);
        AV[j] = pack2(s_bv[2*j], s_bv[2*j+1]);
    }
    const float* mrow = s_mri + t * 101;
    #pragma unroll 2
    for (int k = 0; k < 96; k++) {
        float mk = mrow[k];
        unsigned long long m2 = pack2(mk, mk);
        const ulonglong2* wf = (const ulonglong2*)(s_w2 + k * 64);
        const ulonglong2* wv = (const ulonglong2*)(s_w2 + k * 64 + 32);
        #pragma unroll
        for (int j = 0; j < 8; j++) {
            ulonglong2 a = wf[j];
            AF[2*j]   = fma2(m2, a.x, AF[2*j]);
            AF[2*j+1] = fma2(m2, a.y, AF[2*j+1]);
        }
        #pragma unroll
        for (int j = 0; j < 8; j++) {
            ulonglong2 q = wv[j];
            AV[2*j]   = fma2(m2, q.x, AV[2*j]);
            AV[2*j+1] = fma2(m2, q.y, AV[2*j+1]);
        }
    }
    float af[32], av[32];
    #pragma unroll
    for (int j = 0; j < 16; j++) {
        unpack2(AF[j], af[2*j], af[2*j+1]);
        unpack2(AV[j], av[2*j], av[2*j+1]);
    }

    float ss = 0.f;
    #pragma unroll
    for (int c = 0; c < 32; c++) ss += af[c] * af[c];
    float inv = 1.f / fmaxf(sqrtf(ss), 1e-12f);
    float al = alpha[0], be = beta[0];
    float sgn = (al >= 0.f) ? 1.f : -1.f;

    // delta-dots vs center 0: high-accuracy argmax (bulk of center cancels exactly)
    float Dm[8];
    Dm[0] = 0.f;
    #pragma unroll
    for (int mm_ = 1; mm_ < 8; mm_++) {
        float d = 0.f;
        #pragma unroll
        for (int c = 0; c < 32; c++) d += s_dc[mm_ * 32 + c] * af[c];
        Dm[mm_] = d;
    }
    float k1 = -1e30f, k2 = -1e30f;
    int m1 = 0, m2i = 0;
    #pragma unroll
    for (int mm_ = 0; mm_ < 8; mm_++) {
        float key = sgn * Dm[mm_];
        if (key > k1) { k2 = k1; m2i = m1; k1 = key; m1 = mm_; }
        else if (key > k2) { k2 = key; m2i = mm_; }
    }
    float zgap = fabsf(al) * (k1 - k2) * inv;

    float sv, sv_disp;
    int bi;
    if (zgap >= FLAG_THR) {
        bi = m1;
        float dot0 = 0.f;
        #pragma unroll
        for (int c = 0; c < 32; c++) dot0 += s_cf[c] * af[c];
        float cosb = (dot0 + Dm[m1]) * inv;
        sv = 1.f / (1.f + expf(-(be + al * cosb)));
        sv_disp = sv;
    } else {
        // rare: df64 conv recheck + fp64 decision/blend (identical to R5 semantics)
        dfloat D[32];
        #pragma unroll
        for (int c = 0; c < 32; c++) { D[c].hi = s_bf[c]; D[c].lo = 0.f; }
        #pragma unroll 1
        for (int k = 0; k < 96; k++) {
            float mk = mrow[k];
            const float* wrow = s_w2 + k * 64;
            #pragma unroll
            for (int c = 0; c < 32; c++)
                D[c] = df_addp1(D[c], wrow[c], mk);
        }
        double afd[32];
        double ssd = 0.0;
        #pragma unroll
        for (int c = 0; c < 32; c++) {
            afd[c] = (double)D[c].hi + (double)D[c].lo;
            ssd += afd[c] * afd[c];
        }
        double invd = 1.0 / fmax(sqrt(ssd), 1e-12);
        double ald = (double)al, bed = (double)be;

        double z1 = -1e300, z2 = -1e300;
        int mm1 = 0, mm2 = 0;
        #pragma unroll 1
        for (int mm_ = 0; mm_ < 8; mm_++) {
            double dd = 0.0;
            #pragma unroll
            for (int c = 0; c < 32; c++) dd += s_cfd[mm_ * 32 + c] * afd[c];
            double zz = bed + ald * (dd * invd);
            if (zz > z1) { z2 = z1; mm2 = mm1; z1 = zz; mm1 = mm_; }
            else if (zz > z2) { z2 = zz; mm2 = mm_; }
        }
        bi = mm1;
        sv = 1.f / (1.f + expf(-(float)z1));
        double g = z1 - z2;
        if (g < THETA) {
            float w = 0.5f + 0.5f * (float)(g / THETA);
            float sv2 = 1.f / (1.f + expf(-(float)z2));
            int slot = atomicAdd(&g_nfix, 1);
            if (slot < MAXFIX) {
                g_fix[slot].bh  = bh;
                g_fix[slot].n   = n0 + t;
                g_fix[slot].m   = mm2;
                g_fix[slot].wsv = (1.f - w) * sv2;
            }
            sv_disp = w * sv;
        } else {
            sv_disp = sv;
        }
    }

    g_sim[bh][n0 + t] = sv_disp;
    g_idx[bh][n0 + t] = (unsigned char)bi;

    float* my_num = s_num4 + (t >> 6) * 256;
    float* my_den = s_den4 + (t >> 6) * 8;
    #pragma unroll
    for (int c = 0; c < 32; c++) atomicAdd(&my_num[bi * 32 + c], sv * av[c]);
    atomicAdd(&my_den[bi], sv);
    __syncthreads();
    float tot = s_num4[t] + s_num4[256 + t] + s_num4[512 + t] + s_num4[768 + t];
    atomicAdd(&((float*)g_num)[bh * 256 + t], tot);
    if (t < 8)
        atomicAdd(&g_den[bh][t], s_den4[t] + s_den4[8 + t] + s_den4[16 + t] + s_den4[24 + t]);
}

// ---------------- kernel 3: agg + fold proj into P ----------------
__global__ void k_P(const float* __restrict__ proj_w) {
    __shared__ float s_pj[32 * 97];
    __shared__ float s_agg[256];
    int bh = blockIdx.x;
    int h = bh & 7;
    int t = threadIdx.x;

    for (int i = t; i < 32 * 96; i += 256) {
        int c = i & 31, o = i >> 5;
        s_pj[c * 97 + o] = proj_w[o * 256 + h * 32 + c];
    }
    {
        int m = t >> 5;
        s_agg[t] = (((const float*)g_num)[bh * 256 + t] + ((const float*)g_cv)[bh * 256 + t])
                 / (g_den[bh][m] + 1.f);
    }
    __syncthreads();
    for (int j = t; j < 8 * 96; j += 256) {
        int m = j / 96, o = j % 96;
        float p = 0.f;
        #pragma unroll
        for (int c = 0; c < 32; c++)
            p += s_pj[c * 97 + o] * s_agg[m * 32 + c];
        g_P[bh][m][o] = p;
    }
}

// ---------------- kernel 4: dispatch + write output ----------------
__global__ void __launch_bounds__(256)
k_out(const float* __restrict__ proj_b, float* __restrict__ out) {
    __shared__ __align__(16) float P_s[8][8][104];
    __shared__ float sim_s[8][256];
    __shared__ unsigned char idx_s[8][256];
    __shared__ float pb_s[96];
    int t  = threadIdx.x;
    int b  = blockIdx.y;
    int n0 = blockIdx.x << 8;

    for (int i = t; i < 8 * 8 * 96; i += 256) {
        int o = i % 96, m = (i / 96) & 7, h = i / 768;
        P_s[h][m][o] = ((float*)g_P)[((b * 8 + h) * 8 + m) * 96 + o];
    }
    for (int i = t; i < 8 * 256; i += 256) {
        int h = i >> 8, v = i & 255;
        sim_s[h][v] = g_sim[b * 8 + h][n0 + v];
        idx_s[h][v] = g_idx[b * 8 + h][n0 + v];
    }
    if (t < 96) pb_s[t] = proj_b[t];
    __syncthreads();

    float acc[96];
    #pragma unroll
    for (int o = 0; o < 96; o++) acc[o] = pb_s[o];

    #pragma unroll
    for (int h = 0; h < 8; h++) {
        float s = sim_s[h][t];
        const float4* Pb = (const float4*)&P_s[h][idx_s[h][t]][0];
        #pragma unroll
        for (int o4 = 0; o4 < 24; o4++) {
            float4 p = Pb[o4];
            acc[o4 * 4 + 0] += s * p.x;
            acc[o4 * 4 + 1] += s * p.y;
            acc[o4 * 4 + 2] += s * p.z;
            acc[o4 * 4 + 3] += s * p.w;
        }
    }
    size_t n = (size_t)n0 + t;
    #pragma unroll
    for (int o = 0; o < 96; o++)
        out[(((size_t)(b * 96 + o)) << 15) + n] = acc[o];
}

// ---------------- kernel 5: secondary-candidate fixups ----------------
__global__ void k_fix(const float* __restrict__ proj_w, float* __restrict__ out) {
    int nf = g_nfix;
    if (nf > MAXFIX) nf = MAXFIX;
    int o = threadIdx.x;   // 0..95
    for (int e = blockIdx.x; e < nf; e += gridDim.x) {
        FixEntry f = g_fix[e];
        int bh = f.bh, h = bh & 7, b = bh >> 3, m = f.m;
        float den = g_den[bh][m] + 1.f;
        float p = 0.f;
        #pragma unroll
        for (int c = 0; c < 32; c++) {
            float agg = (g_num[bh][m][c] + g_cv[bh][m][c]) / den;
            p += proj_w[o * 256 + h * 32 + c] * agg;
        }
        atomicAdd(&out[(((size_t)(b * 96 + o)) << 15) + f.n], f.wsv * p);
    }
}

// ---------------- launch ----------------
extern "C" void kernel_launch(void* const* d_in, const int* in_sizes, int n_in,
                              void* d_out, int out_size) {
    const float* PET     = (const float*)d_in[0];
    const float* MRI     = (const float*)d_in[1];
    const float* f_pet_w = (const float*)d_in[2];
    const float* f_pet_b = (const float*)d_in[3];
    const float* f_mri_w = (const float*)d_in[4];
    const float* f_mri_b = (const float*)d_in[5];
    const float* v_pet_w = (const float*)d_in[6];
    const float* v_pet_b = (const float*)d_in[7];
    const float* v_mri_w = (const float*)d_in[8];
    const float* v_mri_b = (const float*)d_in[9];
    const float* proj_w  = (const float*)d_in[10];
    const float* proj_b  = (const float*)d_in[11];
    const float* alpha   = (const float*)d_in[12];
    const float* beta    = (const float*)d_in[13];
    float* out = (float*)d_out;

    size_t smem_main = SM_MAIN_FLOATS * sizeof(float);   // ~136.6 KB
    cudaFuncSetAttribute(k_main, cudaFuncAttributeMaxDynamicSharedMemorySize, (int)smem_main);

    k_pool<<<1536, 128>>>(PET);
    k_centers<<<16, 256>>>(f_pet_w, f_pet_b, v_pet_w, v_pet_b);
    k_main<<<dim3(128, 8, 2), 256, smem_main>>>(MRI, f_mri_w, f_mri_b,
                                                v_mri_w, v_mri_b, alpha, beta);
    k_P<<<16, 256>>>(proj_w);
    k_out<<<dim3(128, 2), 256>>>(proj_b, out);
    k_fix<<<8, 96>>>(proj_w, out);
}